// round 12
// baseline (speedup 1.0000x reference)
#include <cuda_runtime.h>
#include <cstdint>

// ---------------------------------------------------------------------------
// AnnularPatchEmbed: out[b,c,j] = fc( sum_{p in ring c} x[b,p] * W[:,p] )
// ALL ring geometry (pixel permutation, chunk table) baked at COMPILE TIME
// via constexpr (exact integer d^2 thresholds == reference masks).
// 3 launches: segmented SGEMM -> parallel reduce -> fc.
// ---------------------------------------------------------------------------

#define IMGSZ 224
#define NPIX  50176
#define NB    64
#define ND    256
#define CK    288        // pixels per GEMM chunk (ring-aligned)
#define MAXC  192        // static bound on chunk count

#define FMA2(c, a, b) asm("fma.rn.f32x2 %0, %1, %2, %0;" : "+l"(c) : "l"(a), "l"(b))
#define PACK2(p, f)   asm("mov.b64 %0, {%1, %1};" : "=l"(p) : "f"(f))
#define UNPACK2(lo, hi, c) asm("mov.b64 {%0, %1}, %2;" : "=f"(lo), "=f"(hi) : "l"(c))

// ------------------------- compile-time geometry ---------------------------
// largest m >= 0 with m*m < t (t in [1, 12769)); binary search, 7 steps.
constexpr int csqrt_lt(int t) {
    int lo = 0, hi = 113;
    while (lo + 1 < hi) {
        int m = (lo + hi) >> 1;
        if (m * m < t) lo = m; else hi = m;
    }
    return lo;
}

struct Tables {
    int perm[NPIX];          // ring-major, row-major pixel order
    int chunkStart[MAXC];
    int chunkLen[MAXC];
    int ringChunkStart[17];
};

constexpr Tables make_tables() {
    Tables T{};
    int pos = 0, nc = 0;
    for (int r = 0; r < 16; r++) {
        int ringBase = pos;
        T.ringChunkStart[r] = nc;
        for (int y = 0; y < IMGSZ; y++) {
            int dy = y - 112, dy2 = dy * dy;
            int t_lo = 49 * r * r - dy2;
            int t_hi = 49 * (r + 1) * (r + 1) - dy2;
            if (t_hi < 1) continue;
            int b = csqrt_lt(t_hi);                          // dx^2 < t_hi
            int a = (t_lo < 1) ? 0 : (csqrt_lt(t_lo) + 1);   // dx^2 >= t_lo
            if (a > b) continue;
            int rowp = y * IMGSZ + 112;
            if (a == 0) {
                for (int dx = -b; dx <= b; dx++) T.perm[pos++] = rowp + dx;
            } else {
                for (int dx = -b; dx <= -a; dx++) T.perm[pos++] = rowp + dx;
                for (int dx = a; dx <= b; dx++)   T.perm[pos++] = rowp + dx;
            }
        }
        int n = pos - ringBase;
        for (int s = 0; s < n; s += CK) {
            T.chunkStart[nc] = ringBase + s;
            T.chunkLen[nc]   = (n - s < CK) ? (n - s) : CK;
            nc++;
        }
    }
    T.ringChunkStart[16] = nc;
    return T;
}

// host-side chunk count (exact grid size, no device readback)
constexpr int count_chunks() {
    int nc = 0;
    for (int r = 0; r < 16; r++) {
        int n = 0;
        for (int y = 0; y < IMGSZ; y++) {
            int dy = y - 112, dy2 = dy * dy;
            int t_lo = 49 * r * r - dy2;
            int t_hi = 49 * (r + 1) * (r + 1) - dy2;
            if (t_hi < 1) continue;
            int b = csqrt_lt(t_hi);
            int a = (t_lo < 1) ? 0 : (csqrt_lt(t_lo) + 1);
            if (a > b) continue;
            n += (a == 0) ? (2 * b + 1) : (2 * (b - a + 1));
        }
        nc += (n + CK - 1) / CK;
    }
    return nc;
}
constexpr int NCH = count_chunks();
static_assert(NCH <= MAXC, "chunk bound");

__device__ const Tables dT = make_tables();   // baked into cubin (~201 KB)

// ------------------------- device scratch (static, no allocs) --------------
__device__ float g_partial[(size_t)MAXC * NB * ND];   // 12.6 MB
__device__ float g_tok[(size_t)NB * 16 * ND];         // 1 MB

// ------------------------- 1) main segmented SGEMM (LDG double-buffer) -----
// Grid (NCH, 2). CTA = one 288-pixel chunk x one 128-wide d half.
// 64(b) x 128(d) tile, 256 threads, f32x2 accs (4 b-pairs x 4 d per thread).
__global__ void __launch_bounds__(256, 2)
k_gemm(const float* __restrict__ X, const float* __restrict__ W) {
    int ch     = blockIdx.x;
    int d0     = blockIdx.y * 128;
    int kStart = dT.chunkStart[ch];
    int kLen   = dT.chunkLen[ch];

    __shared__ __align__(16) float xs[2][16 * 68];
    __shared__ __align__(16) float ws[2][16 * 132];
    __shared__ int pSm[CK];

    int tid = threadIdx.x;
    for (int i = tid; i < CK; i += 256)
        pSm[i] = (i < kLen) ? dT.perm[kStart + i] : -1;
    __syncthreads();

    int tb = tid >> 5;       // 0..7  -> 8 b-rows each (4 pairs)
    int td = tid & 31;       // 0..31 -> 4 d-cols each
    int numTiles = (kLen + 15) >> 4;

    unsigned long long acc[4][4];     // [b-pair][d]
    #pragma unroll
    for (int i = 0; i < 4; i++)
        #pragma unroll
        for (int j = 0; j < 4; j++) acc[i][j] = 0ULL;

    float xr[4], wr[8];

    auto loadTile = [&](int t) {
        int k0 = t << 4;
        #pragma unroll
        for (int j = 0; j < 4; j++) {
            int i = tid + j * 256;
            int b = i >> 4, kk = i & 15;
            int p = pSm[k0 + kk];
            xr[j] = (p >= 0) ? X[b * NPIX + p] : 0.f;
        }
        #pragma unroll
        for (int j = 0; j < 8; j++) {
            int i = tid + j * 256;
            int d = i >> 4, kk = i & 15;
            int p = pSm[k0 + kk];
            wr[j] = (p >= 0) ? W[(size_t)(d0 + d) * NPIX + p] : 0.f;
        }
    };
    auto storeTile = [&](int buf) {
        #pragma unroll
        for (int j = 0; j < 4; j++) {
            int i = tid + j * 256;
            int b = i >> 4, kk = i & 15;
            xs[buf][kk * 68 + b] = xr[j];
        }
        #pragma unroll
        for (int j = 0; j < 8; j++) {
            int i = tid + j * 256;
            int d = i >> 4, kk = i & 15;
            ws[buf][kk * 132 + d] = wr[j];
        }
    };

    loadTile(0);
    storeTile(0);

    for (int t = 0; t < numTiles; t++) {
        __syncthreads();
        int buf = t & 1;
        if (t + 1 < numTiles) loadTile(t + 1);

        #pragma unroll
        for (int kk = 0; kk < 16; kk++) {
            const float* xrow = &xs[buf][kk * 68 + tb * 8];
            ulonglong2 xa = *(const ulonglong2*)xrow;         // b-pairs 0,1
            ulonglong2 xc = *(const ulonglong2*)(xrow + 4);   // b-pairs 2,3
            float4 wv = *(const float4*)&ws[buf][kk * 132 + td * 4];
            unsigned long long wp0, wp1, wp2, wp3;
            PACK2(wp0, wv.x); PACK2(wp1, wv.y); PACK2(wp2, wv.z); PACK2(wp3, wv.w);
            FMA2(acc[0][0], xa.x, wp0); FMA2(acc[0][1], xa.x, wp1);
            FMA2(acc[0][2], xa.x, wp2); FMA2(acc[0][3], xa.x, wp3);
            FMA2(acc[1][0], xa.y, wp0); FMA2(acc[1][1], xa.y, wp1);
            FMA2(acc[1][2], xa.y, wp2); FMA2(acc[1][3], xa.y, wp3);
            FMA2(acc[2][0], xc.x, wp0); FMA2(acc[2][1], xc.x, wp1);
            FMA2(acc[2][2], xc.x, wp2); FMA2(acc[2][3], xc.x, wp3);
            FMA2(acc[3][0], xc.y, wp0); FMA2(acc[3][1], xc.y, wp1);
            FMA2(acc[3][2], xc.y, wp2); FMA2(acc[3][3], xc.y, wp3);
        }
        __syncthreads();
        if (t + 1 < numTiles) storeTile((t + 1) & 1);
    }

    // unpack + write partials (float4 per b-row)
    size_t base = (size_t)ch * (NB * ND);
    #pragma unroll
    for (int bp = 0; bp < 4; bp++) {
        float lo0, hi0, lo1, hi1, lo2, hi2, lo3, hi3;
        UNPACK2(lo0, hi0, acc[bp][0]);
        UNPACK2(lo1, hi1, acc[bp][1]);
        UNPACK2(lo2, hi2, acc[bp][2]);
        UNPACK2(lo3, hi3, acc[bp][3]);
        int b0 = tb * 8 + bp * 2;
        float4 vlo = make_float4(lo0, lo1, lo2, lo3);
        float4 vhi = make_float4(hi0, hi1, hi2, hi3);
        *(float4*)&g_partial[base + (size_t)b0 * ND + d0 + td * 4] = vlo;
        *(float4*)&g_partial[base + (size_t)(b0 + 1) * ND + d0 + td * 4] = vhi;
    }
}

// ------------------------- 2) parallel chunk reduction ---------------------
// Grid (64 b, 16 rings), 256 threads (one per d). 8-way MLP over chunks.
// (R8-measured config: 8.0 us)
__global__ void __launch_bounds__(256)
k_reduce() {
    int b = blockIdx.x, c = blockIdx.y, tid = threadIdx.x;
    int c0 = dT.ringChunkStart[c], c1 = dT.ringChunkStart[c + 1];
    size_t brow = (size_t)b * ND + tid;
    float s[8];
    #pragma unroll
    for (int q = 0; q < 8; q++) s[q] = 0.f;
    int ch = c0;
    for (; ch + 7 < c1; ch += 8) {
        #pragma unroll
        for (int q = 0; q < 8; q++)
            s[q] += g_partial[(size_t)(ch + q) * (NB * ND) + brow];
    }
    for (int q = 0; ch < c1; ch++, q++)
        s[q] += g_partial[(size_t)ch * (NB * ND) + brow];
    float r = ((s[0] + s[1]) + (s[2] + s[3])) + ((s[4] + s[5]) + (s[6] + s[7]));
    g_tok[((size_t)b * 16 + c) * ND + tid] = r;
}

// ------------------------- 3) fc projection (256->192) ---------------------
// Grid 64 (one block per b), 256 threads (192 compute).
__global__ void __launch_bounds__(256)
k_fc(const float* __restrict__ fcw, const float* __restrict__ fcb,
     float* __restrict__ out) {
    __shared__ __align__(16) float tok[256 * 20];   // [d][c] padded to 20

    int b = blockIdx.x, tid = threadIdx.x;
    for (int i = tid; i < 16 * ND; i += 256) {
        int c = i >> 8, d = i & 255;
        tok[d * 20 + c] = g_tok[((size_t)b * 16 + c) * ND + d];
    }
    __syncthreads();

    if (tid < 192) {
        int j = tid;
        unsigned long long acc[8];
        #pragma unroll
        for (int q = 0; q < 8; q++) acc[q] = 0ULL;

        const float4* fw4 = (const float4*)(fcw + (size_t)j * ND);
        #pragma unroll 4
        for (int d4 = 0; d4 < 64; d4++) {
            float4 wv = fw4[d4];
            #pragma unroll
            for (int s = 0; s < 4; s++) {
                int d = d4 * 4 + s;
                float w = (s == 0) ? wv.x : (s == 1) ? wv.y : (s == 2) ? wv.z : wv.w;
                unsigned long long wp;
                PACK2(wp, w);
                const ulonglong2* tp = (const ulonglong2*)&tok[d * 20];
                ulonglong2 t0 = tp[0], t1 = tp[1], t2 = tp[2], t3 = tp[3];
                FMA2(acc[0], t0.x, wp); FMA2(acc[1], t0.y, wp);
                FMA2(acc[2], t1.x, wp); FMA2(acc[3], t1.y, wp);
                FMA2(acc[4], t2.x, wp); FMA2(acc[5], t2.y, wp);
                FMA2(acc[6], t3.x, wp); FMA2(acc[7], t3.y, wp);
            }
        }
        float bias = fcb[j];
        #pragma unroll
        for (int q = 0; q < 8; q++) {
            float lo, hi;
            UNPACK2(lo, hi, acc[q]);
            out[((size_t)b * 16 + 2 * q) * 192 + j]     = lo + bias;
            out[((size_t)b * 16 + 2 * q + 1) * 192 + j] = hi + bias;
        }
    }
}

// ---------------------------------------------------------------------------
extern "C" void kernel_launch(void* const* d_in, const int* in_sizes, int n_in,
                              void* d_out, int out_size) {
    const float* x   = (const float*)d_in[0];  // [64, 224, 224]
    const float* tw  = (const float*)d_in[1];  // [256, 1, 224, 224]
    const float* fcw = (const float*)d_in[2];  // [192, 256]
    const float* fcb = (const float*)d_in[3];  // [192]
    // d_in[4] (masks) unused: rings derived analytically (exact).
    float* out = (float*)d_out;                // [64, 16, 192]

    k_gemm<<<dim3(NCH, 2), 256>>>(x, tw);
    k_reduce<<<dim3(64, 16), 256>>>();
    k_fc<<<64, 256>>>(fcw, fcb, out);
}

// round 14
// speedup vs baseline: 1.0285x; 1.0285x over previous
#include <cuda_runtime.h>
#include <cstdint>

// ---------------------------------------------------------------------------
// AnnularPatchEmbed: out[b,c,j] = fc( sum_{p in ring c} x[b,p] * W[:,p] )
// Ring geometry baked at COMPILE TIME (exact integer d^2 thresholds).
// 3 launches: segmented SGEMM (KTILE=32, cp.async 2-stage, 1 barrier-pair
// per tile, dynamic smem) -> parallel reduce -> fc.
// ---------------------------------------------------------------------------

#define IMGSZ 224
#define NPIX  50176
#define NB    64
#define ND    256
#define CK    288        // pixels per GEMM chunk (ring-aligned)
#define MAXC  192        // static bound on chunk count
#define KT    32         // k-tile

// dynamic smem layout (floats): xs[2][KT*68], ws[2][KT*132], pSm[CK] ints
#define XS_FLOATS (2 * KT * 68)      // 4352
#define WS_FLOATS (2 * KT * 132)     // 8448
#define SMEM_BYTES ((XS_FLOATS + WS_FLOATS) * 4 + CK * 4)   // 52352

#define FMA2(c, a, b) asm("fma.rn.f32x2 %0, %1, %2, %0;" : "+l"(c) : "l"(a), "l"(b))
#define PACK2(p, f)   asm("mov.b64 %0, {%1, %1};" : "=l"(p) : "f"(f))
#define UNPACK2(lo, hi, c) asm("mov.b64 {%0, %1}, %2;" : "=f"(lo), "=f"(hi) : "l"(c))
#define CP4(dst, src, sz) \
    asm volatile("cp.async.ca.shared.global [%0], [%1], 4, %2;" \
                 :: "r"(dst), "l"(src), "r"(sz))
#define CP_COMMIT() asm volatile("cp.async.commit_group;" ::: "memory")
#define CP_WAIT0()  asm volatile("cp.async.wait_group 0;" ::: "memory")

// ------------------------- compile-time geometry ---------------------------
constexpr int csqrt_lt(int t) {      // largest m >= 0 with m*m < t
    int lo = 0, hi = 113;
    while (lo + 1 < hi) {
        int m = (lo + hi) >> 1;
        if (m * m < t) lo = m; else hi = m;
    }
    return lo;
}

struct Tables {
    int perm[NPIX];          // ring-major, row-major pixel order
    int chunkStart[MAXC];
    int chunkLen[MAXC];
    int ringChunkStart[17];
};

constexpr Tables make_tables() {
    Tables T{};
    int pos = 0, nc = 0;
    for (int r = 0; r < 16; r++) {
        int ringBase = pos;
        T.ringChunkStart[r] = nc;
        for (int y = 0; y < IMGSZ; y++) {
            int dy = y - 112, dy2 = dy * dy;
            int t_lo = 49 * r * r - dy2;
            int t_hi = 49 * (r + 1) * (r + 1) - dy2;
            if (t_hi < 1) continue;
            int b = csqrt_lt(t_hi);
            int a = (t_lo < 1) ? 0 : (csqrt_lt(t_lo) + 1);
            if (a > b) continue;
            int rowp = y * IMGSZ + 112;
            if (a == 0) {
                for (int dx = -b; dx <= b; dx++) T.perm[pos++] = rowp + dx;
            } else {
                for (int dx = -b; dx <= -a; dx++) T.perm[pos++] = rowp + dx;
                for (int dx = a; dx <= b; dx++)   T.perm[pos++] = rowp + dx;
            }
        }
        int n = pos - ringBase;
        for (int s = 0; s < n; s += CK) {
            T.chunkStart[nc] = ringBase + s;
            T.chunkLen[nc]   = (n - s < CK) ? (n - s) : CK;
            nc++;
        }
    }
    T.ringChunkStart[16] = nc;
    return T;
}

constexpr int count_chunks() {
    int nc = 0;
    for (int r = 0; r < 16; r++) {
        int n = 0;
        for (int y = 0; y < IMGSZ; y++) {
            int dy = y - 112, dy2 = dy * dy;
            int t_lo = 49 * r * r - dy2;
            int t_hi = 49 * (r + 1) * (r + 1) - dy2;
            if (t_hi < 1) continue;
            int b = csqrt_lt(t_hi);
            int a = (t_lo < 1) ? 0 : (csqrt_lt(t_lo) + 1);
            if (a > b) continue;
            n += (a == 0) ? (2 * b + 1) : (2 * (b - a + 1));
        }
        nc += (n + CK - 1) / CK;
    }
    return nc;
}
constexpr int NCH = count_chunks();
static_assert(NCH <= MAXC, "chunk bound");

__device__ const Tables dT = make_tables();   // baked into cubin (~201 KB)

// ------------------------- device scratch (static, no allocs) --------------
__device__ float g_partial[(size_t)MAXC * NB * ND];   // 12.6 MB
__device__ float g_tok[(size_t)NB * 16 * ND];         // 1 MB

// ------------------------- 1) main segmented SGEMM -------------------------
// Grid (NCH, 2). CTA = one 288-pixel chunk x one 128-wide d half.
// 64(b) x 128(d) tile, 256 threads. KTILE=32, cp.async 2-stage pipeline,
// ONE barrier-pair per tile. f32x2 accs (4 b-pairs x 4 d per thread).
// Dynamic smem: 52352 B (xs | ws | pSm).
__global__ void __launch_bounds__(256, 2)
k_gemm(const float* __restrict__ X, const float* __restrict__ W) {
    extern __shared__ __align__(16) float smem[];
    float* xs  = smem;                         // [2][KT*68]
    float* ws  = smem + XS_FLOATS;             // [2][KT*132]
    int*   pSm = (int*)(smem + XS_FLOATS + WS_FLOATS);   // [CK]

    int ch     = blockIdx.x;
    int d0     = blockIdx.y * 128;
    int kStart = dT.chunkStart[ch];
    int kLen   = dT.chunkLen[ch];

    int tid = threadIdx.x;
    for (int i = tid; i < CK; i += 256)
        pSm[i] = (i < kLen) ? dT.perm[kStart + i] : 0;   // clamp; sz=0 masks
    __syncthreads();

    int tb = tid >> 5;       // 0..7  -> 8 b-rows each (4 pairs)
    int td = tid & 31;       // 0..31 -> 4 d-cols each
    int numTiles = (kLen + KT - 1) / KT;

    uint32_t xsA = (uint32_t)__cvta_generic_to_shared(xs);
    uint32_t wsA = (uint32_t)__cvta_generic_to_shared(ws);

    auto issueTile = [&](int t) {
        if (t < numTiles) {
            int k0 = t * KT;
            int s  = t & 1;
            #pragma unroll
            for (int j = 0; j < 8; j++) {                 // X: 64 b x 32 kk
                int i = tid + j * 256;
                int b = i >> 5, kk = i & 31;
                int gk = k0 + kk;
                int sz = (gk < kLen) ? 4 : 0;
                const float* src = X + b * NPIX + pSm[gk];
                uint32_t dst = xsA + (uint32_t)(s * (KT * 68) + kk * 68 + b) * 4u;
                CP4(dst, src, sz);
            }
            #pragma unroll
            for (int j = 0; j < 16; j++) {                // W: 128 d x 32 kk
                int i = tid + j * 256;
                int d = i >> 5, kk = i & 31;
                int gk = k0 + kk;
                int sz = (gk < kLen) ? 4 : 0;
                const float* src = W + (size_t)(d0 + d) * NPIX + pSm[gk];
                uint32_t dst = wsA + (uint32_t)(s * (KT * 132) + kk * 132 + d) * 4u;
                CP4(dst, src, sz);
            }
        }
        CP_COMMIT();
    };

    unsigned long long acc[4][4];     // [b-pair][d]
    #pragma unroll
    for (int i = 0; i < 4; i++)
        #pragma unroll
        for (int j = 0; j < 4; j++) acc[i][j] = 0ULL;

    issueTile(0);

    for (int t = 0; t < numTiles; t++) {
        CP_WAIT0();                 // my tile-t bytes are in smem
        __syncthreads();            // everyone's bytes visible; buf t^1 free
        issueTile(t + 1);           // stream next tile during compute

        int s = t & 1;
        const float* xb = xs + s * (KT * 68);
        const float* wb = ws + s * (KT * 132);
        #pragma unroll
        for (int kk = 0; kk < KT; kk++) {
            const float* xrow = xb + kk * 68 + tb * 8;
            ulonglong2 xa = *(const ulonglong2*)xrow;         // b-pairs 0,1
            ulonglong2 xc = *(const ulonglong2*)(xrow + 4);   // b-pairs 2,3
            float4 wv = *(const float4*)(wb + kk * 132 + td * 4);
            unsigned long long wp0, wp1, wp2, wp3;
            PACK2(wp0, wv.x); PACK2(wp1, wv.y); PACK2(wp2, wv.z); PACK2(wp3, wv.w);
            FMA2(acc[0][0], xa.x, wp0); FMA2(acc[0][1], xa.x, wp1);
            FMA2(acc[0][2], xa.x, wp2); FMA2(acc[0][3], xa.x, wp3);
            FMA2(acc[1][0], xa.y, wp0); FMA2(acc[1][1], xa.y, wp1);
            FMA2(acc[1][2], xa.y, wp2); FMA2(acc[1][3], xa.y, wp3);
            FMA2(acc[2][0], xc.x, wp0); FMA2(acc[2][1], xc.x, wp1);
            FMA2(acc[2][2], xc.x, wp2); FMA2(acc[2][3], xc.x, wp3);
            FMA2(acc[3][0], xc.y, wp0); FMA2(acc[3][1], xc.y, wp1);
            FMA2(acc[3][2], xc.y, wp2); FMA2(acc[3][3], xc.y, wp3);
        }
        __syncthreads();            // compute on buf s done; safe to refill
    }

    // unpack + write partials (float4 per b-row)
    size_t base = (size_t)ch * (NB * ND);
    #pragma unroll
    for (int bp = 0; bp < 4; bp++) {
        float lo0, hi0, lo1, hi1, lo2, hi2, lo3, hi3;
        UNPACK2(lo0, hi0, acc[bp][0]);
        UNPACK2(lo1, hi1, acc[bp][1]);
        UNPACK2(lo2, hi2, acc[bp][2]);
        UNPACK2(lo3, hi3, acc[bp][3]);
        int b0 = tb * 8 + bp * 2;
        float4 vlo = make_float4(lo0, lo1, lo2, lo3);
        float4 vhi = make_float4(hi0, hi1, hi2, hi3);
        *(float4*)&g_partial[base + (size_t)b0 * ND + d0 + td * 4] = vlo;
        *(float4*)&g_partial[base + (size_t)(b0 + 1) * ND + d0 + td * 4] = vhi;
    }
}

// ------------------------- 2) parallel chunk reduction ---------------------
// Grid (64 b, 16 rings), 256 threads (one per d). 8-way MLP over chunks.
__global__ void __launch_bounds__(256)
k_reduce() {
    int b = blockIdx.x, c = blockIdx.y, tid = threadIdx.x;
    int c0 = dT.ringChunkStart[c], c1 = dT.ringChunkStart[c + 1];
    size_t brow = (size_t)b * ND + tid;
    float s[8];
    #pragma unroll
    for (int q = 0; q < 8; q++) s[q] = 0.f;
    int ch = c0;
    for (; ch + 7 < c1; ch += 8) {
        #pragma unroll
        for (int q = 0; q < 8; q++)
            s[q] += g_partial[(size_t)(ch + q) * (NB * ND) + brow];
    }
    for (int q = 0; ch < c1; ch++, q++)
        s[q] += g_partial[(size_t)ch * (NB * ND) + brow];
    float r = ((s[0] + s[1]) + (s[2] + s[3])) + ((s[4] + s[5]) + (s[6] + s[7]));
    g_tok[((size_t)b * 16 + c) * ND + tid] = r;
}

// ------------------------- 3) fc projection (256->192) ---------------------
// Grid 64 (one block per b), 256 threads (192 compute).
__global__ void __launch_bounds__(256)
k_fc(const float* __restrict__ fcw, const float* __restrict__ fcb,
     float* __restrict__ out) {
    __shared__ __align__(16) float tok[256 * 20];   // [d][c] padded to 20

    int b = blockIdx.x, tid = threadIdx.x;
    for (int i = tid; i < 16 * ND; i += 256) {
        int c = i >> 8, d = i & 255;
        tok[d * 20 + c] = g_tok[((size_t)b * 16 + c) * ND + d];
    }
    __syncthreads();

    if (tid < 192) {
        int j = tid;
        unsigned long long acc[8];
        #pragma unroll
        for (int q = 0; q < 8; q++) acc[q] = 0ULL;

        const float4* fw4 = (const float4*)(fcw + (size_t)j * ND);
        #pragma unroll 4
        for (int d4 = 0; d4 < 64; d4++) {
            float4 wv = fw4[d4];
            #pragma unroll
            for (int s = 0; s < 4; s++) {
                int d = d4 * 4 + s;
                float w = (s == 0) ? wv.x : (s == 1) ? wv.y : (s == 2) ? wv.z : wv.w;
                unsigned long long wp;
                PACK2(wp, w);
                const ulonglong2* tp = (const ulonglong2*)&tok[d * 20];
                ulonglong2 t0 = tp[0], t1 = tp[1], t2 = tp[2], t3 = tp[3];
                FMA2(acc[0], t0.x, wp); FMA2(acc[1], t0.y, wp);
                FMA2(acc[2], t1.x, wp); FMA2(acc[3], t1.y, wp);
                FMA2(acc[4], t2.x, wp); FMA2(acc[5], t2.y, wp);
                FMA2(acc[6], t3.x, wp); FMA2(acc[7], t3.y, wp);
            }
        }
        float bias = fcb[j];
        #pragma unroll
        for (int q = 0; q < 8; q++) {
            float lo, hi;
            UNPACK2(lo, hi, acc[q]);
            out[((size_t)b * 16 + 2 * q) * 192 + j]     = lo + bias;
            out[((size_t)b * 16 + 2 * q + 1) * 192 + j] = hi + bias;
        }
    }
}

// ---------------------------------------------------------------------------
extern "C" void kernel_launch(void* const* d_in, const int* in_sizes, int n_in,
                              void* d_out, int out_size) {
    const float* x   = (const float*)d_in[0];  // [64, 224, 224]
    const float* tw  = (const float*)d_in[1];  // [256, 1, 224, 224]
    const float* fcw = (const float*)d_in[2];  // [192, 256]
    const float* fcb = (const float*)d_in[3];  // [192]
    // d_in[4] (masks) unused: rings derived analytically (exact).
    float* out = (float*)d_out;                // [64, 16, 192]

    // host-side attribute set (non-stream, non-allocating; capture-safe)
    cudaFuncSetAttribute(k_gemm, cudaFuncAttributeMaxDynamicSharedMemorySize,
                         SMEM_BYTES);

    k_gemm<<<dim3(NCH, 2), 256, SMEM_BYTES>>>(x, tw);
    k_reduce<<<dim3(64, 16), 256>>>();
    k_fc<<<64, 256>>>(fcw, fcb, out);
}